// round 12
// baseline (speedup 1.0000x reference)
#include <cuda_runtime.h>
#include <cstdint>

#define NN 2048
#define BB 4
#define THREADS 128
#define ROWS_PER_BLOCK 4                         // 2 row-groups x 2 rows
#define BLOCKS_PER_BATCH (NN / ROWS_PER_BLOCK)   // 512
#define CHUNK 512
#define NWIN 32                                  // 4 chunks x 8 windows
#define NSTAGES 4
#define STAGE_BYTES 512                          // [Wr0|Ar0|Wr1|Ar1] x 128B

typedef unsigned long long u64;

__device__ __forceinline__ void fma2(u64& d, u64 a, u64 b) {
    asm("fma.rn.f32x2 %0, %1, %2, %0;" : "+l"(d) : "l"(a), "l"(b));
}
__device__ __forceinline__ u64 pack2(float lo, float hi) {
    u64 r;
    asm("mov.b64 %0, {%1, %2};" : "=l"(r) : "f"(lo), "f"(hi));
    return r;
}
__device__ __forceinline__ void unpack2(float& lo, float& hi, u64 v) {
    asm("mov.b64 {%0, %1}, %2;" : "=f"(lo), "=f"(hi) : "l"(v));
}
__device__ __forceinline__ u64 add2(u64 a, u64 b) {
    u64 r;
    asm("add.rn.f32x2 %0, %1, %2;" : "=l"(r) : "l"(a), "l"(b));
    return r;
}
__device__ __forceinline__ void cp16(uint32_t dst_smem, const void* src) {
    asm volatile("cp.async.cg.shared.global [%0], [%1], 16;"
                 :: "r"(dst_smem), "l"(src));
}
#define CP_COMMIT() asm volatile("cp.async.commit_group;")
#define CP_WAIT3()  asm volatile("cp.async.wait_group 3;")

__global__ __launch_bounds__(THREADS, 9)
void kuramoto_kernel(const float* __restrict__ W,
                     const float* __restrict__ alpha,
                     const float4* __restrict__ theta,
                     const float4* __restrict__ gamma,
                     float4* __restrict__ out) {
    __shared__ float4 s_sh[CHUNK];                                // 8 KB
    __shared__ float4 c_sh[CHUNK];                                // 8 KB
    __shared__ __align__(16) char stage[4][NSTAGES][STAGE_BYTES]; // 8 KB
    __shared__ u64 red[4][2][4];                                  // [warp][r][4]

    const int b    = blockIdx.x / BLOCKS_PER_BATCH;
    const int row0 = (blockIdx.x % BLOCKS_PER_BATCH) * ROWS_PER_BLOCK;
    const int base = b * NN;

    const int warp   = threadIdx.x >> 5;
    const int lane   = threadIdx.x & 31;
    const int rowgrp = warp >> 1;             // rows {0,1} / {2,3} of block
    const int jhalf  = warp & 1;              // alternating 256-j slice per chunk
    const int i0     = row0 + rowgrp * 2;     // first of this warp's 2 rows

    const float* __restrict__ Wr = W     + (size_t)(base + i0) * NN;
    const float* __restrict__ Ar = alpha + (size_t)(base + i0) * NN;

    // cp.async lane mapping: q = lane>>3 -> [W r0][A r0][W r1][A r1]
    const int  q      = lane >> 3;
    const float* __restrict__ cp_base = (q & 1) ? Ar : Wr;
    const size_t cp_off = (size_t)(q >> 1) * NN + 4 * (lane & 7);

    const uint32_t my_stage =
        (uint32_t)__cvta_generic_to_shared(&stage[warp][0][0]) + lane * 16;
    const char* stage_rd = &stage[warp][0][0];

    // window w: chunk = w>>3, within-chunk slice = jhalf*256 + (w&7)*32
    #define GOFF(w) (((w) >> 3) * CHUNK + jhalf * 256 + ((w) & 7) * 32)

    u64 P01[2], P23[2], Q01[2], Q23[2];
    #pragma unroll
    for (int r = 0; r < 2; ++r) { P01[r] = 0; P23[r] = 0; Q01[r] = 0; Q23[r] = 0; }

    // Prologue: prefetch windows 0..3 (all within chunk 0)
    #pragma unroll
    for (int w = 0; w < NSTAGES; ++w) {
        cp16(my_stage + w * STAGE_BYTES, cp_base + cp_off + GOFF(w));
        CP_COMMIT();
    }

    for (int w = 0; w < NWIN; ++w) {
        // Rebuild sin/cos table at chunk boundaries (8 block barriers total)
        if ((w & 7) == 0) {
            __syncthreads();
            const int ch = w >> 3;
            #pragma unroll
            for (int t = 0; t < CHUNK; t += THREADS) {
                const int idx = t + threadIdx.x;
                const float4 th = theta[base + ch * CHUNK + idx];
                float4 s, c;
                __sincosf(th.x, &s.x, &c.x);
                __sincosf(th.y, &s.y, &c.y);
                __sincosf(th.z, &s.z, &c.z);
                __sincosf(th.w, &s.w, &c.w);
                s_sh[idx] = s;
                c_sh[idx] = c;
            }
            __syncthreads();
        }

        CP_WAIT3();            // window w's group complete (3 stay in flight)
        __syncwarp();          // intra-warp visibility of staged bytes

        const int slot = w % NSTAGES;
        const int jloc = jhalf * 256 + (w & 7) * 32 + lane;   // chunk-local j

        const ulonglong2 sp = *reinterpret_cast<const ulonglong2*>(&s_sh[jloc]);
        const ulonglong2 cp = *reinterpret_cast<const ulonglong2*>(&c_sh[jloc]);
        const char* st = stage_rd + slot * STAGE_BYTES;

        #pragma unroll
        for (int r = 0; r < 2; ++r) {
            const float wv = *reinterpret_cast<const float*>(st + r * 256 + lane * 4);
            const float av = *reinterpret_cast<const float*>(st + r * 256 + 128 + lane * 4);
            float sa, ca;
            __sincosf(av, &sa, &ca);
            const float Av = wv * ca;            // W * cos(alpha)
            const float Bv = wv * sa;            // W * sin(alpha)
            const u64 Av2  = pack2(Av, Av);
            const u64 Bv2  = pack2(Bv, Bv);
            const u64 nBv2 = pack2(-Bv, -Bv);
            // P += Av*c + Bv*s ;  Q += Av*s - Bv*c   (packed d-pairs)
            fma2(P01[r], Av2, cp.x);  fma2(P01[r], Bv2, sp.x);
            fma2(P23[r], Av2, cp.y);  fma2(P23[r], Bv2, sp.y);
            fma2(Q01[r], Av2, sp.x);  fma2(Q01[r], nBv2, cp.x);
            fma2(Q23[r], Av2, sp.y);  fma2(Q23[r], nBv2, cp.y);
        }

        __syncwarp();          // all lanes done reading slot before overwrite
        if (w + NSTAGES < NWIN) {
            cp16(my_stage + slot * STAGE_BYTES, cp_base + cp_off + GOFF(w + NSTAGES));
        }
        CP_COMMIT();           // keep group accounting uniform
    }

    // Butterfly: reduce both rows' packed sums across the 32 lanes
    #pragma unroll
    for (int off = 16; off > 0; off >>= 1) {
        #pragma unroll
        for (int r = 0; r < 2; ++r) {
            P01[r] = add2(P01[r], __shfl_xor_sync(0xffffffffu, P01[r], off));
            P23[r] = add2(P23[r], __shfl_xor_sync(0xffffffffu, P23[r], off));
            Q01[r] = add2(Q01[r], __shfl_xor_sync(0xffffffffu, Q01[r], off));
            Q23[r] = add2(Q23[r], __shfl_xor_sync(0xffffffffu, Q23[r], off));
        }
    }

    if (lane == 0) {
        #pragma unroll
        for (int r = 0; r < 2; ++r) {
            red[warp][r][0] = P01[r];  red[warp][r][1] = P23[r];
            red[warp][r][2] = Q01[r];  red[warp][r][3] = Q23[r];
        }
    }
    __syncthreads();

    // 4 threads: one output row each; combine the two j-half warps
    if (threadIdx.x < ROWS_PER_BLOCK) {
        const int g = threadIdx.x >> 1;      // row-group
        const int r = threadIdx.x & 1;       // row within group
        const int i = row0 + g * 2 + r;

        const u64 p01 = add2(red[2 * g][r][0], red[2 * g + 1][r][0]);
        const u64 p23 = add2(red[2 * g][r][1], red[2 * g + 1][r][1]);
        const u64 q01 = add2(red[2 * g][r][2], red[2 * g + 1][r][2]);
        const u64 q23 = add2(red[2 * g][r][3], red[2 * g + 1][r][3]);

        float P0, P1, P2, P3, Q0, Q1, Q2, Q3;
        unpack2(P0, P1, p01); unpack2(P2, P3, p23);
        unpack2(Q0, Q1, q01); unpack2(Q2, Q3, q23);

        const float invn = 1.0f / (float)NN;     // COUPLING / N
        const float4 g4 = gamma[base + i];
        const float4 th = theta[base + i];
        float4 si, ci;
        __sincosf(th.x, &si.x, &ci.x);
        __sincosf(th.y, &si.y, &ci.y);
        __sincosf(th.z, &si.z, &ci.z);
        __sincosf(th.w, &si.w, &ci.w);

        // theta_next = gamma + (1/N)(c_i*Q - s_i*P)   (theta cancels, DT=ATTR=1)
        float n0 = g4.x + invn * (ci.x * Q0 - si.x * P0);
        float n1 = g4.y + invn * (ci.y * Q1 - si.y * P1);
        float n2 = g4.z + invn * (ci.z * Q2 - si.z * P2);
        float n3 = g4.w + invn * (ci.w * Q3 - si.w * P3);

        float nrm = sqrtf(n0 * n0 + n1 * n1 + n2 * n2 + n3 * n3);
        float inv = 1.0f / fmaxf(nrm, 1e-6f);
        out[base + i] = make_float4(n0 * inv, n1 * inv, n2 * inv, n3 * inv);
    }
}

extern "C" void kernel_launch(void* const* d_in, const int* in_sizes, int n_in,
                              void* d_out, int out_size) {
    const float* theta = (const float*)d_in[0];   // [B, N, 4]
    const float* gamma = (const float*)d_in[1];   // [B, N, 4]
    const float* W     = (const float*)d_in[2];   // [B, N, N]
    const float* alpha = (const float*)d_in[3];   // [B, N, N]
    float* out = (float*)d_out;                   // [B, N, 4]

    // R8 structure at doubled grid: 2048 blocks x 128 threads, 2 rows/warp,
    // 9 CTAs/SM (~36 warps) for latency hiding; table machinery unchanged.
    kuramoto_kernel<<<BB * BLOCKS_PER_BATCH, THREADS>>>(
        W, alpha, (const float4*)theta, (const float4*)gamma, (float4*)out);
}

// round 13
// speedup vs baseline: 1.6046x; 1.6046x over previous
#include <cuda_runtime.h>
#include <cstdint>

#define NN 2048
#define BB 4
#define THREADS 128
#define ROWS_PER_BLOCK 8                         // 2 row-groups x 4 rows
#define BLOCKS_PER_BATCH (NN / ROWS_PER_BLOCK)   // 256
#define CHUNK 256                                // table chunk (8 KB smem)
#define NCHUNKS (NN / CHUNK)                     // 8
#define NWIN 32                                  // 8 chunks x 4 windows
#define NSTAGES 5
#define STAGE_BYTES 1024                         // 4 rows x 32 j x 4B x 2 arrays

typedef unsigned long long u64;

__device__ __forceinline__ void fma2(u64& d, u64 a, u64 b) {
    asm("fma.rn.f32x2 %0, %1, %2, %0;" : "+l"(d) : "l"(a), "l"(b));
}
__device__ __forceinline__ u64 pack2(float lo, float hi) {
    u64 r;
    asm("mov.b64 %0, {%1, %2};" : "=l"(r) : "f"(lo), "f"(hi));
    return r;
}
__device__ __forceinline__ void unpack2(float& lo, float& hi, u64 v) {
    asm("mov.b64 {%0, %1}, %2;" : "=f"(lo), "=f"(hi) : "l"(v));
}
__device__ __forceinline__ u64 add2(u64 a, u64 b) {
    u64 r;
    asm("add.rn.f32x2 %0, %1, %2;" : "=l"(r) : "l"(a), "l"(b));
    return r;
}
__device__ __forceinline__ void cp16(uint32_t dst_smem, const void* src) {
    asm volatile("cp.async.cg.shared.global [%0], [%1], 16;"
                 :: "r"(dst_smem), "l"(src));
}
#define CP_COMMIT() asm volatile("cp.async.commit_group;")
#define CP_WAIT4()  asm volatile("cp.async.wait_group 4;")

__global__ __launch_bounds__(THREADS, 7)
void kuramoto_kernel(const float* __restrict__ W,
                     const float* __restrict__ alpha,
                     const float4* __restrict__ theta,
                     const float4* __restrict__ gamma,
                     float4* __restrict__ out) {
    __shared__ float4 s_sh[CHUNK];                                // 4 KB
    __shared__ float4 c_sh[CHUNK];                                // 4 KB
    __shared__ __align__(16) char stage[4][NSTAGES][STAGE_BYTES]; // 20 KB
    __shared__ u64 red[4][4][4];                                  // [warp][r][4]

    const int b    = blockIdx.x / BLOCKS_PER_BATCH;
    const int row0 = (blockIdx.x % BLOCKS_PER_BATCH) * ROWS_PER_BLOCK;
    const int base = b * NN;

    const int warp   = threadIdx.x >> 5;
    const int lane   = threadIdx.x & 31;
    const int rowgrp = warp >> 1;             // rows 0-3 / 4-7
    const int jpart  = warp & 1;              // chunk j-half (128 j)
    const int i0     = row0 + rowgrp * 4;     // first of this warp's 4 rows

    const float* __restrict__ Wr = W     + (size_t)(base + i0) * NN;
    const float* __restrict__ Ar = alpha + (size_t)(base + i0) * NN;

    // This lane's LDGSTS source: row = lane>>3, j-seg = 4*(lane&7)
    const size_t src_row_off = (size_t)(lane >> 3) * NN + 4 * (lane & 7);
    const uint32_t my_stage =
        (uint32_t)__cvta_generic_to_shared(&stage[warp][0][0]) + lane * 16;
    const char* stage_rd = &stage[warp][0][0];

    // window w: chunk = w>>2, within-chunk slice = jpart*128 + (w&3)*32
    #define GOFF(w) (((w) >> 2) * CHUNK + jpart * 128 + ((w) & 3) * 32)

    u64 P01[4], P23[4], Q01[4], Q23[4];
    #pragma unroll
    for (int r = 0; r < 4; ++r) { P01[r] = 0; P23[r] = 0; Q01[r] = 0; Q23[r] = 0; }

    // Prologue: prefetch windows 0..4 (global loads, no table dependency)
    #pragma unroll
    for (int w = 0; w < NSTAGES; ++w) {
        const uint32_t dst = my_stage + w * STAGE_BYTES;
        cp16(dst,       Wr + src_row_off + GOFF(w));
        cp16(dst + 512, Ar + src_row_off + GOFF(w));
        CP_COMMIT();
    }

    for (int w = 0; w < NWIN; ++w) {
        // Rebuild sin/cos table at chunk boundaries
        if ((w & 3) == 0) {
            __syncthreads();   // all warps done reading the previous table
            const int ch = w >> 2;
            #pragma unroll
            for (int t = 0; t < CHUNK; t += THREADS) {
                const int idx = t + threadIdx.x;
                const float4 th = theta[base + ch * CHUNK + idx];
                float4 s, c;
                __sincosf(th.x, &s.x, &c.x);
                __sincosf(th.y, &s.y, &c.y);
                __sincosf(th.z, &s.z, &c.z);
                __sincosf(th.w, &s.w, &c.w);
                s_sh[idx] = s;
                c_sh[idx] = c;
            }
            __syncthreads();   // table visible to all warps
        }

        // Table read depends only on the table — hoist above the pipeline wait
        const int jloc = jpart * 128 + (w & 3) * 32 + lane;   // chunk-local j
        const ulonglong2 sp = *reinterpret_cast<const ulonglong2*>(&s_sh[jloc]);
        const ulonglong2 cp = *reinterpret_cast<const ulonglong2*>(&c_sh[jloc]);

        CP_WAIT4();            // window w's group complete (4 stay in flight)
        __syncwarp();          // intra-warp visibility of staged bytes

        const int slot = w % NSTAGES;
        const char* st = stage_rd + slot * STAGE_BYTES;

        #pragma unroll
        for (int r = 0; r < 4; ++r) {
            const float wv = *reinterpret_cast<const float*>(st + r * 128 + lane * 4);
            const float av = *reinterpret_cast<const float*>(st + 512 + r * 128 + lane * 4);
            float sa, ca;
            __sincosf(av, &sa, &ca);
            const float Av = wv * ca;            // W * cos(alpha)
            const float Bv = wv * sa;            // W * sin(alpha)
            const u64 Av2  = pack2(Av, Av);
            const u64 Bv2  = pack2(Bv, Bv);
            const u64 nBv2 = pack2(-Bv, -Bv);
            // P += Av*c + Bv*s ;  Q += Av*s - Bv*c   (packed d-pairs)
            fma2(P01[r], Av2, cp.x);  fma2(P01[r], Bv2, sp.x);
            fma2(P23[r], Av2, cp.y);  fma2(P23[r], Bv2, sp.y);
            fma2(Q01[r], Av2, sp.x);  fma2(Q01[r], nBv2, cp.x);
            fma2(Q23[r], Av2, sp.y);  fma2(Q23[r], nBv2, cp.y);
        }

        __syncwarp();          // all lanes done reading slot before overwrite
        if (w + NSTAGES < NWIN) {
            const uint32_t dst = my_stage + slot * STAGE_BYTES;
            cp16(dst,       Wr + src_row_off + GOFF(w + NSTAGES));
            cp16(dst + 512, Ar + src_row_off + GOFF(w + NSTAGES));
        }
        CP_COMMIT();           // keep group accounting uniform
    }

    // Butterfly: reduce all 4 rows' packed sums across the 32 lanes
    #pragma unroll
    for (int off = 16; off > 0; off >>= 1) {
        #pragma unroll
        for (int r = 0; r < 4; ++r) {
            P01[r] = add2(P01[r], __shfl_xor_sync(0xffffffffu, P01[r], off));
            P23[r] = add2(P23[r], __shfl_xor_sync(0xffffffffu, P23[r], off));
            Q01[r] = add2(Q01[r], __shfl_xor_sync(0xffffffffu, Q01[r], off));
            Q23[r] = add2(Q23[r], __shfl_xor_sync(0xffffffffu, Q23[r], off));
        }
    }

    if (lane == 0) {
        #pragma unroll
        for (int r = 0; r < 4; ++r) {
            red[warp][r][0] = P01[r];  red[warp][r][1] = P23[r];
            red[warp][r][2] = Q01[r];  red[warp][r][3] = Q23[r];
        }
    }
    __syncthreads();

    // 8 threads: one output row each; combine the two j-half warps
    if (threadIdx.x < ROWS_PER_BLOCK) {
        const int g = threadIdx.x >> 2;      // row-group
        const int r = threadIdx.x & 3;       // row within group
        const int i = row0 + g * 4 + r;

        const u64 p01 = add2(red[2 * g][r][0], red[2 * g + 1][r][0]);
        const u64 p23 = add2(red[2 * g][r][1], red[2 * g + 1][r][1]);
        const u64 q01 = add2(red[2 * g][r][2], red[2 * g + 1][r][2]);
        const u64 q23 = add2(red[2 * g][r][3], red[2 * g + 1][r][3]);

        float P0, P1, P2, P3, Q0, Q1, Q2, Q3;
        unpack2(P0, P1, p01); unpack2(P2, P3, p23);
        unpack2(Q0, Q1, q01); unpack2(Q2, Q3, q23);

        const float invn = 1.0f / (float)NN;     // COUPLING / N
        const float4 g4 = gamma[base + i];
        const float4 th = theta[base + i];
        float4 si, ci;
        __sincosf(th.x, &si.x, &ci.x);
        __sincosf(th.y, &si.y, &ci.y);
        __sincosf(th.z, &si.z, &ci.z);
        __sincosf(th.w, &si.w, &ci.w);

        // theta_next = gamma + (1/N)(c_i*Q - s_i*P)   (theta cancels, DT=ATTR=1)
        float n0 = g4.x + invn * (ci.x * Q0 - si.x * P0);
        float n1 = g4.y + invn * (ci.y * Q1 - si.y * P1);
        float n2 = g4.z + invn * (ci.z * Q2 - si.z * P2);
        float n3 = g4.w + invn * (ci.w * Q3 - si.w * P3);

        float nrm = sqrtf(n0 * n0 + n1 * n1 + n2 * n2 + n3 * n3);
        float inv = 1.0f / fmaxf(nrm, 1e-6f);
        out[base + i] = make_float4(n0 * inv, n1 * inv, n2 * inv, n3 * inv);
    }
}

extern "C" void kernel_launch(void* const* d_in, const int* in_sizes, int n_in,
                              void* d_out, int out_size) {
    const float* theta = (const float*)d_in[0];   // [B, N, 4]
    const float* gamma = (const float*)d_in[1];   // [B, N, 4]
    const float* W     = (const float*)d_in[2];   // [B, N, N]
    const float* alpha = (const float*)d_in[3];   // [B, N, N]
    float* out = (float*)d_out;                   // [B, N, 4]

    // R8 shape with a deeper cp.async pipeline: 5 stages / wait_group 4
    // (4 KB in flight per warp), smaller 256-entry table chunks to fit smem,
    // warp-scope per-window sync, 7 CTAs/SM single wave.
    kuramoto_kernel<<<BB * BLOCKS_PER_BATCH, THREADS>>>(
        W, alpha, (const float4*)theta, (const float4*)gamma, (float4*)out);
}

// round 14
// speedup vs baseline: 1.6169x; 1.0077x over previous
#include <cuda_runtime.h>
#include <cstdint>

#define NN 2048
#define BB 4
#define THREADS 128
#define ROWS_PER_BLOCK 8                         // 2 row-groups x 4 rows
#define BLOCKS_PER_BATCH (NN / ROWS_PER_BLOCK)   // 256
#define CHUNK 256                                // table chunk entries
#define NCH 8                                    // chunks per batch
#define NWIN 32                                  // 8 chunks x 4 windows
#define NSTAGES 3
#define STAGE_BYTES 1024                         // 4 rows x 32 j x 4B x 2 arrays

typedef unsigned long long u64;

// Global sincos table of theta (built once by pre-kernel)
__device__ float4 g_s[BB * NN];
__device__ float4 g_c[BB * NN];

__global__ void sincos_kernel(const float4* __restrict__ theta) {
    int idx = blockIdx.x * blockDim.x + threadIdx.x;
    if (idx >= BB * NN) return;
    float4 t = theta[idx];
    float4 s, c;
    __sincosf(t.x, &s.x, &c.x);
    __sincosf(t.y, &s.y, &c.y);
    __sincosf(t.z, &s.z, &c.z);
    __sincosf(t.w, &s.w, &c.w);
    g_s[idx] = s;
    g_c[idx] = c;
}

__device__ __forceinline__ void fma2(u64& d, u64 a, u64 b) {
    asm("fma.rn.f32x2 %0, %1, %2, %0;" : "+l"(d) : "l"(a), "l"(b));
}
__device__ __forceinline__ u64 pack2(float lo, float hi) {
    u64 r;
    asm("mov.b64 %0, {%1, %2};" : "=l"(r) : "f"(lo), "f"(hi));
    return r;
}
__device__ __forceinline__ void unpack2(float& lo, float& hi, u64 v) {
    asm("mov.b64 {%0, %1}, %2;" : "=f"(lo), "=f"(hi) : "l"(v));
}
__device__ __forceinline__ u64 add2(u64 a, u64 b) {
    u64 r;
    asm("add.rn.f32x2 %0, %1, %2;" : "=l"(r) : "l"(a), "l"(b));
    return r;
}
__device__ __forceinline__ void cp16(uint32_t dst_smem, const void* src) {
    asm volatile("cp.async.cg.shared.global [%0], [%1], 16;"
                 :: "r"(dst_smem), "l"(src));
}
#define CP_COMMIT() asm volatile("cp.async.commit_group;")
#define CP_WAIT2()  asm volatile("cp.async.wait_group 2;")

__global__ __launch_bounds__(THREADS, 7)
void kuramoto_kernel(const float* __restrict__ W,
                     const float* __restrict__ alpha,
                     const float4* __restrict__ gamma,
                     float4* __restrict__ out) {
    __shared__ __align__(16) float4 s_tb[2][CHUNK];               // 8 KB
    __shared__ __align__(16) float4 c_tb[2][CHUNK];               // 8 KB
    __shared__ __align__(16) char stage[4][NSTAGES][STAGE_BYTES]; // 12 KB
    __shared__ u64 red[4][4][4];                                  // [warp][r][4]

    const int b    = blockIdx.x / BLOCKS_PER_BATCH;
    const int row0 = (blockIdx.x % BLOCKS_PER_BATCH) * ROWS_PER_BLOCK;
    const int base = b * NN;

    const int tid    = threadIdx.x;
    const int warp   = tid >> 5;
    const int lane   = tid & 31;
    const int rowgrp = warp >> 1;             // rows 0-3 / 4-7
    const int jpart  = warp & 1;              // chunk j-half (128 j)
    const int i0     = row0 + rowgrp * 4;     // first of this warp's 4 rows

    const float* __restrict__ Wr = W     + (size_t)(base + i0) * NN;
    const float* __restrict__ Ar = alpha + (size_t)(base + i0) * NN;

    // W/alpha LDGSTS source: row = lane>>3, j-seg = 4*(lane&7)
    const size_t src_row_off = (size_t)(lane >> 3) * NN + 4 * (lane & 7);
    const uint32_t my_stage =
        (uint32_t)__cvta_generic_to_shared(&stage[warp][0][0]) + lane * 16;
    const char* stage_rd = &stage[warp][0][0];

    // Table prefetch destinations (per-thread, 2 cp16 per array per chunk)
    const uint32_t tbS0 = (uint32_t)__cvta_generic_to_shared(&s_tb[0][0]) + tid * 16;
    const uint32_t tbC0 = (uint32_t)__cvta_generic_to_shared(&c_tb[0][0]) + tid * 16;
    const uint32_t tbufBytes = (uint32_t)(CHUNK * sizeof(float4));   // 4096

    // window w: chunk = w>>2, within-chunk slice = jpart*128 + (w&3)*32
    #define GOFF(w) (((w) >> 2) * CHUNK + jpart * 128 + ((w) & 3) * 32)

    #define PREF_TABLE(ch) do {                                              \
        const uint32_t _bo = ((ch) & 1) * tbufBytes;                         \
        const float4* _ss = &g_s[base + (ch) * CHUNK + tid];                 \
        const float4* _cc = &g_c[base + (ch) * CHUNK + tid];                 \
        cp16(tbS0 + _bo,        _ss);                                        \
        cp16(tbS0 + _bo + 2048, _ss + 128);                                  \
        cp16(tbC0 + _bo,        _cc);                                        \
        cp16(tbC0 + _bo + 2048, _cc + 128);                                  \
    } while (0)

    #define PREF_WIN(w) do {                                                 \
        const uint32_t _dst = my_stage + ((w) % NSTAGES) * STAGE_BYTES;      \
        cp16(_dst,       Wr + src_row_off + GOFF(w));                        \
        cp16(_dst + 512, Ar + src_row_off + GOFF(w));                        \
    } while (0)

    u64 P01[4], P23[4], Q01[4], Q23[4];
    #pragma unroll
    for (int r = 0; r < 4; ++r) { P01[r] = 0; P23[r] = 0; Q01[r] = 0; Q23[r] = 0; }

    // Prologue: G0 = table ch0 + win0, G1 = table ch1 + win1, G2 = win2
    PREF_TABLE(0); PREF_WIN(0); CP_COMMIT();
    PREF_TABLE(1); PREF_WIN(1); CP_COMMIT();
    PREF_WIN(2);                CP_COMMIT();

    for (int w = 0; w < NWIN; ++w) {
        const int ch = w >> 2;

        CP_WAIT2();            // window w's group + this chunk's table group done
        if ((w & 3) == 0) {
            __syncthreads();   // table buf[ch&1] visible; buf[(ch+1)&1] free
            // Prefetch the NEXT chunk's table a full chunk ahead (ch>=1; 0,1
            // were loaded in the prologue). Joins this iteration's group.
            if (ch >= 1 && ch + 1 < NCH) PREF_TABLE(ch + 1);
        } else {
            __syncwarp();      // intra-warp visibility of staged window bytes
        }

        // ---- compute window w ----
        const int jloc = jpart * 128 + (w & 3) * 32 + lane;   // chunk-local j
        const ulonglong2 sp =
            *reinterpret_cast<const ulonglong2*>(&s_tb[ch & 1][jloc]);
        const ulonglong2 cp =
            *reinterpret_cast<const ulonglong2*>(&c_tb[ch & 1][jloc]);
        const char* st = stage_rd + (w % NSTAGES) * STAGE_BYTES;

        #pragma unroll
        for (int r = 0; r < 4; ++r) {
            const float wv = *reinterpret_cast<const float*>(st + r * 128 + lane * 4);
            const float av = *reinterpret_cast<const float*>(st + 512 + r * 128 + lane * 4);
            float sa, ca;
            __sincosf(av, &sa, &ca);
            const float Av = wv * ca;            // W * cos(alpha)
            const float Bv = wv * sa;            // W * sin(alpha)
            const u64 Av2  = pack2(Av, Av);
            const u64 Bv2  = pack2(Bv, Bv);
            const u64 nBv2 = pack2(-Bv, -Bv);
            // P += Av*c + Bv*s ;  Q += Av*s - Bv*c   (packed d-pairs)
            fma2(P01[r], Av2, cp.x);  fma2(P01[r], Bv2, sp.x);
            fma2(P23[r], Av2, cp.y);  fma2(P23[r], Bv2, sp.y);
            fma2(Q01[r], Av2, sp.x);  fma2(Q01[r], nBv2, cp.x);
            fma2(Q23[r], Av2, sp.y);  fma2(Q23[r], nBv2, cp.y);
        }

        __syncwarp();          // all lanes done reading slot before overwrite
        if (w + NSTAGES < NWIN) PREF_WIN(w + NSTAGES);
        CP_COMMIT();           // one group per iteration (window [+ table])
    }

    // Butterfly: reduce all 4 rows' packed sums across the 32 lanes
    #pragma unroll
    for (int off = 16; off > 0; off >>= 1) {
        #pragma unroll
        for (int r = 0; r < 4; ++r) {
            P01[r] = add2(P01[r], __shfl_xor_sync(0xffffffffu, P01[r], off));
            P23[r] = add2(P23[r], __shfl_xor_sync(0xffffffffu, P23[r], off));
            Q01[r] = add2(Q01[r], __shfl_xor_sync(0xffffffffu, Q01[r], off));
            Q23[r] = add2(Q23[r], __shfl_xor_sync(0xffffffffu, Q23[r], off));
        }
    }

    if (lane == 0) {
        #pragma unroll
        for (int r = 0; r < 4; ++r) {
            red[warp][r][0] = P01[r];  red[warp][r][1] = P23[r];
            red[warp][r][2] = Q01[r];  red[warp][r][3] = Q23[r];
        }
    }
    __syncthreads();

    // 8 threads: one output row each; combine the two j-half warps
    if (tid < ROWS_PER_BLOCK) {
        const int g = tid >> 2;              // row-group
        const int r = tid & 3;               // row within group
        const int i = row0 + g * 4 + r;

        const u64 p01 = add2(red[2 * g][r][0], red[2 * g + 1][r][0]);
        const u64 p23 = add2(red[2 * g][r][1], red[2 * g + 1][r][1]);
        const u64 q01 = add2(red[2 * g][r][2], red[2 * g + 1][r][2]);
        const u64 q23 = add2(red[2 * g][r][3], red[2 * g + 1][r][3]);

        float P0, P1, P2, P3, Q0, Q1, Q2, Q3;
        unpack2(P0, P1, p01); unpack2(P2, P3, p23);
        unpack2(Q0, Q1, q01); unpack2(Q2, Q3, q23);

        const float invn = 1.0f / (float)NN;     // COUPLING / N
        const float4 g4 = gamma[base + i];
        const float4 si = g_s[base + i];
        const float4 ci = g_c[base + i];

        // theta_next = gamma + (1/N)(c_i*Q - s_i*P)   (theta cancels, DT=ATTR=1)
        float n0 = g4.x + invn * (ci.x * Q0 - si.x * P0);
        float n1 = g4.y + invn * (ci.y * Q1 - si.y * P1);
        float n2 = g4.z + invn * (ci.z * Q2 - si.z * P2);
        float n3 = g4.w + invn * (ci.w * Q3 - si.w * P3);

        float nrm = sqrtf(n0 * n0 + n1 * n1 + n2 * n2 + n3 * n3);
        float inv = 1.0f / fmaxf(nrm, 1e-6f);
        out[base + i] = make_float4(n0 * inv, n1 * inv, n2 * inv, n3 * inv);
    }
}

extern "C" void kernel_launch(void* const* d_in, const int* in_sizes, int n_in,
                              void* d_out, int out_size) {
    const float* theta = (const float*)d_in[0];   // [B, N, 4]
    const float* gamma = (const float*)d_in[1];   // [B, N, 4]
    const float* W     = (const float*)d_in[2];   // [B, N, N]
    const float* alpha = (const float*)d_in[3];   // [B, N, N]
    float* out = (float*)d_out;                   // [B, N, 4]

    // Pre-kernel: sincos table once (kills 33% redundant MUFU per block)
    sincos_kernel<<<(BB * NN + 255) / 256, 256>>>((const float4*)theta);

    // Main kernel: double-buffered cp.async table prefetch (one chunk ahead,
    // barriers become near-free, DRAM never drains) + R8 window pipeline.
    kuramoto_kernel<<<BB * BLOCKS_PER_BATCH, THREADS>>>(
        W, alpha, (const float4*)gamma, (float4*)out);
}